// round 8
// baseline (speedup 1.0000x reference)
#include <cuda_runtime.h>

// ============================================================================
// Compile-time network machinery (all stages 0-1-verified at compile time).
//  - Batcher odd-even mergesort (power-of-2) + prefix restriction.
//  - Generalized odd-even merge on index lists (oem2).
//  - Global program over 144 slots: 12 column sorts, 5 pair merges, 4 quad
//    merges, interval-pruned finals for 8 pixels; COPY ops for multiply-
//    consumed values; one global backward slice with op-level pruning
//    (min-only / max-only / both) and copy liveness.
//  - Interval pruning theorem: for rank-12 of union(A sorted 20, B sorted 5),
//    A[i] has union position in [i, i+5]; A[0..6] always below rank 12,
//    A[13..19] always above; answer = index 5 of sorted(A[7..12] u B).
// ============================================================================

struct P8 { unsigned char a, b; };
struct Op { unsigned char t, a, b, op; };  // t: 0=CE, 1=COPY(a <- b)
struct CE3 { unsigned char a, b, op; };    // op: 0=both, 1=min-only, 2=max-only

constexpr void oem_merge(int lo, int n, int r, P8* out, int& cnt) {
    int m = r * 2;
    if (m < n) {
        oem_merge(lo,     n, m, out, cnt);
        oem_merge(lo + r, n, m, out, cnt);
        for (int i = lo + r; i + r < lo + n; i += m)
            out[cnt++] = P8{(unsigned char)i, (unsigned char)(i + r)};
    } else {
        out[cnt++] = P8{(unsigned char)lo, (unsigned char)(lo + r)};
    }
}

constexpr void oem_sort(int lo, int n, P8* out, int& cnt) {
    if (n > 1) {
        int m = n / 2;
        oem_sort(lo,     m, out, cnt);
        oem_sort(lo + m, m, out, cnt);
        oem_merge(lo, n, 1, out, cnt);
    }
}

// ---- sort-5 network: Batcher sort-8 restricted to slots < 5 (9 CEs).
struct Net5 { int n; P8 p[24]; };

constexpr Net5 build_sort5() {
    P8 all[64] = {};
    int cnt = 0;
    oem_sort(0, 8, all, cnt);
    Net5 s = {};
    for (int i = 0; i < cnt; ++i)
        if (all[i].a < 5 && all[i].b < 5)
            s.p[s.n++] = all[i];
    return s;
}

constexpr bool verify_sort5(const Net5& s) {
    for (int m = 0; m < 32; ++m) {
        int v[5] = {};
        for (int k = 0; k < 5; ++k) v[k] = (m >> k) & 1;
        for (int i = 0; i < s.n; ++i) {
            int a = s.p[i].a, b = s.p[i].b;
            if (v[a] > v[b]) { int t = v[a]; v[a] = v[b]; v[b] = t; }
        }
        for (int k = 0; k + 1 < 5; ++k)
            if (v[k] > v[k + 1]) return false;
    }
    return true;
}

static_assert(verify_sort5(build_sort5()), "sort5 network invalid");

// ---- Generalized odd-even merge on index lists (Knuth 5.2.2-style).
constexpr void oem2(const int* A, int m, const int* B, int n, int* Z,
                    P8* ce, int& cnt) {
    if (m == 0) { for (int i = 0; i < n; ++i) Z[i] = B[i]; return; }
    if (n == 0) { for (int i = 0; i < m; ++i) Z[i] = A[i]; return; }
    if (m == 1 && n == 1) {
        ce[cnt++] = P8{(unsigned char)A[0], (unsigned char)B[0]};
        Z[0] = A[0]; Z[1] = B[0];
        return;
    }
    int Ae[25] = {}, Ao[25] = {}, Be[25] = {}, Bo[25] = {};
    int nae = 0, nao = 0, nbe = 0, nbo = 0;
    for (int i = 0; i < m; ++i) { if (i & 1) Ao[nao++] = A[i]; else Ae[nae++] = A[i]; }
    for (int i = 0; i < n; ++i) { if (i & 1) Bo[nbo++] = B[i]; else Be[nbe++] = B[i]; }
    int E[25] = {}, O[25] = {};
    oem2(Ae, nae, Be, nbe, E, ce, cnt);
    oem2(Ao, nao, Bo, nbo, O, ce, cnt);
    int ne = nae + nbe, no = nao + nbo;
    Z[0] = E[0];
    int zi = 1;
    int i = 0;
    for (; i < no && i + 1 < ne; ++i) {
        ce[cnt++] = P8{(unsigned char)O[i], (unsigned char)E[i + 1]};
        Z[zi++] = O[i];
        Z[zi++] = E[i + 1];
    }
    for (; i < no; ++i) Z[zi++] = O[i];
    for (int j = i + 1; j < ne; ++j) Z[zi++] = E[j];
}

// Exhaustive 0-1 verification of one merge stage over a 144-slot space.
constexpr bool verify_merge144(const P8* ce, int ibeg, int iend,
                               const int* A, int m, const int* B, int n,
                               const int* Z) {
    for (int i = 0; i <= m; ++i) {
        for (int j = 0; j <= n; ++j) {
            int v[144] = {};
            for (int k = 0; k < m; ++k) v[A[k]] = (k >= m - i) ? 1 : 0;
            for (int k = 0; k < n; ++k) v[B[k]] = (k >= n - j) ? 1 : 0;
            for (int t = ibeg; t < iend; ++t) {
                int a = ce[t].a, b = ce[t].b;
                if (v[a] > v[b]) { int tmp = v[a]; v[a] = v[b]; v[b] = tmp; }
            }
            for (int k = 0; k + 1 < m + n; ++k)
                if (v[Z[k]] > v[Z[k + 1]]) return false;
        }
    }
    return true;
}

// ---- Boundary network: sort-25 sliced for {12,13} with op-level pruning.
struct Net { int n; CE3 p[256]; };

constexpr Net slice_net25(const P8* ce, int cnt, const bool* outputs_needed) {
    bool need[25] = {};
    for (int i = 0; i < 25; ++i) need[i] = outputs_needed[i];
    signed char op[256] = {};
    bool keep[256] = {};
    for (int i = cnt - 1; i >= 0; --i) {
        bool na = need[ce[i].a], nb = need[ce[i].b];
        if (!na && !nb) continue;
        keep[i] = true;
        op[i] = (na && nb) ? 0 : (na ? 1 : 2);
        need[ce[i].a] = true;
        need[ce[i].b] = true;
    }
    Net net = {};
    for (int i = 0; i < cnt; ++i)
        if (keep[i])
            net.p[net.n++] = CE3{ce[i].a, ce[i].b, (unsigned char)op[i]};
    return net;
}

constexpr Net build_boundary_net() {
    P8 all[256] = {};
    int cnt = 0;
    oem_sort(0, 32, all, cnt);
    P8 filt[256] = {};
    int fc = 0;
    for (int i = 0; i < cnt; ++i)
        if (all[i].a < 25 && all[i].b < 25)
            filt[fc++] = all[i];
    bool outs[25] = {};
    outs[12] = true;
    outs[13] = true;
    return slice_net25(filt, fc, outs);
}

__device__ constexpr Net BNET = build_boundary_net();

// ---- Global interior program over 144 slots, 8 pixels per thread.
// Slots 0..59: sorted local columns c0..c11 (col j at 5j..5j+4).
// 60..89: copies of cols {2,4,5,6,7,9}. 90..119: copies of m34,m56,m78.
// 120..143: quad windows WA,WB,WC,WD (6 each).
struct Prog { int n; Op p[600]; unsigned char outslot[8]; bool ok; };

constexpr Prog build_prog() {
    Op ops[640] = {};
    int oc = 0;
    bool ok = true;

    // Column sorts.
    {
        Net5 s5 = build_sort5();
        for (int j = 0; j < 12; ++j)
            for (int i = 0; i < s5.n; ++i)
                ops[oc++] = Op{0, (unsigned char)(5 * j + s5.p[i].a),
                                  (unsigned char)(5 * j + s5.p[i].b), 0};
    }

    int C[12][5] = {};
    for (int j = 0; j < 12; ++j)
        for (int k = 0; k < 5; ++k) C[j][k] = 5 * j + k;

    // Copies of cols consumed by pair merges but reused by finals.
    int CP[12][5] = {};
    {
        const int src[6] = {2, 4, 5, 6, 7, 9};
        for (int ci = 0; ci < 6; ++ci)
            for (int k = 0; k < 5; ++k) {
                int slot = 60 + 5 * ci + k;
                CP[src[ci]][k] = slot;
                ops[oc++] = Op{1, (unsigned char)slot, (unsigned char)C[src[ci]][k], 0};
            }
    }

    int Z12[10] = {}, Z34[10] = {}, Z56[10] = {}, Z78[10] = {}, Z910[10] = {};

    // Pair merges (in place over their column slots).
    {
        P8 t[160] = {}; int tc = 0;
        oem2(C[1], 5, C[2], 5, Z12, t, tc);
        ok = ok && verify_merge144(t, 0, tc, C[1], 5, C[2], 5, Z12);
        for (int i = 0; i < tc; ++i) ops[oc++] = Op{0, t[i].a, t[i].b, 0};
    }
    {
        P8 t[160] = {}; int tc = 0;
        oem2(C[3], 5, C[4], 5, Z34, t, tc);
        ok = ok && verify_merge144(t, 0, tc, C[3], 5, C[4], 5, Z34);
        for (int i = 0; i < tc; ++i) ops[oc++] = Op{0, t[i].a, t[i].b, 0};
    }
    {
        P8 t[160] = {}; int tc = 0;
        oem2(C[5], 5, C[6], 5, Z56, t, tc);
        ok = ok && verify_merge144(t, 0, tc, C[5], 5, C[6], 5, Z56);
        for (int i = 0; i < tc; ++i) ops[oc++] = Op{0, t[i].a, t[i].b, 0};
    }
    {
        P8 t[160] = {}; int tc = 0;
        oem2(C[7], 5, C[8], 5, Z78, t, tc);
        ok = ok && verify_merge144(t, 0, tc, C[7], 5, C[8], 5, Z78);
        for (int i = 0; i < tc; ++i) ops[oc++] = Op{0, t[i].a, t[i].b, 0};
    }
    {
        P8 t[160] = {}; int tc = 0;
        oem2(C[9], 5, C[10], 5, Z910, t, tc);
        ok = ok && verify_merge144(t, 0, tc, C[9], 5, C[10], 5, Z910);
        for (int i = 0; i < tc; ++i) ops[oc++] = Op{0, t[i].a, t[i].b, 0};
    }

    // Copies of m34, m56, m78 (each feeds two quads).
    int T34[10] = {}, T56[10] = {}, T78[10] = {};
    for (int k = 0; k < 10; ++k) { T34[k] = 90 + k;  ops[oc++] = Op{1, (unsigned char)(90 + k),  (unsigned char)Z34[k], 0}; }
    for (int k = 0; k < 10; ++k) { T56[k] = 100 + k; ops[oc++] = Op{1, (unsigned char)(100 + k), (unsigned char)Z56[k], 0}; }
    for (int k = 0; k < 10; ++k) { T78[k] = 110 + k; ops[oc++] = Op{1, (unsigned char)(110 + k), (unsigned char)Z78[k], 0}; }

    // Quad merges: QA=cols1-4, QB=cols3-6, QC=cols5-8, QD=cols7-10.
    int QA[20] = {}, QB[20] = {}, QC[20] = {}, QD[20] = {};
    {
        P8 t[160] = {}; int tc = 0;
        oem2(Z12, 10, Z34, 10, QA, t, tc);
        ok = ok && verify_merge144(t, 0, tc, Z12, 10, Z34, 10, QA);
        for (int i = 0; i < tc; ++i) ops[oc++] = Op{0, t[i].a, t[i].b, 0};
    }
    {
        P8 t[160] = {}; int tc = 0;
        oem2(T34, 10, Z56, 10, QB, t, tc);
        ok = ok && verify_merge144(t, 0, tc, T34, 10, Z56, 10, QB);
        for (int i = 0; i < tc; ++i) ops[oc++] = Op{0, t[i].a, t[i].b, 0};
    }
    {
        P8 t[160] = {}; int tc = 0;
        oem2(T56, 10, Z78, 10, QC, t, tc);
        ok = ok && verify_merge144(t, 0, tc, T56, 10, Z78, 10, QC);
        for (int i = 0; i < tc; ++i) ops[oc++] = Op{0, t[i].a, t[i].b, 0};
    }
    {
        P8 t[160] = {}; int tc = 0;
        oem2(T78, 10, Z910, 10, QD, t, tc);
        ok = ok && verify_merge144(t, 0, tc, T78, 10, Z910, 10, QD);
        for (int i = 0; i < tc; ++i) ops[oc++] = Op{0, t[i].a, t[i].b, 0};
    }

    // Quad windows [7..12] -> copies (each quad feeds two finals).
    int WA[6] = {}, WB[6] = {}, WC[6] = {}, WD[6] = {};
    int A1[6] = {}, A3[6] = {}, A5[6] = {}, A7[6] = {};
    for (int k = 0; k < 6; ++k) {
        WA[k] = 120 + k; ops[oc++] = Op{1, (unsigned char)(120 + k), (unsigned char)QA[7 + k], 0};
        A1[k] = QA[7 + k];
    }
    for (int k = 0; k < 6; ++k) {
        WB[k] = 126 + k; ops[oc++] = Op{1, (unsigned char)(126 + k), (unsigned char)QB[7 + k], 0};
        A3[k] = QB[7 + k];
    }
    for (int k = 0; k < 6; ++k) {
        WC[k] = 132 + k; ops[oc++] = Op{1, (unsigned char)(132 + k), (unsigned char)QC[7 + k], 0};
        A5[k] = QC[7 + k];
    }
    for (int k = 0; k < 6; ++k) {
        WD[k] = 138 + k; ops[oc++] = Op{1, (unsigned char)(138 + k), (unsigned char)QD[7 + k], 0};
        A7[k] = QD[7 + k];
    }

    unsigned char outs[8] = {};

    // Finals: px j uses cols j..j+4 = quad window + one extra sorted column.
    {
        int ZF[11] = {}; P8 t[160] = {}; int tc = 0;       // px0: WA + c0
        oem2(WA, 6, C[0], 5, ZF, t, tc);
        ok = ok && verify_merge144(t, 0, tc, WA, 6, C[0], 5, ZF);
        for (int i = 0; i < tc; ++i) ops[oc++] = Op{0, t[i].a, t[i].b, 0};
        outs[0] = (unsigned char)ZF[5];
    }
    {
        int ZF[11] = {}; P8 t[160] = {}; int tc = 0;       // px1: QA win + c5 copy
        oem2(A1, 6, CP[5], 5, ZF, t, tc);
        ok = ok && verify_merge144(t, 0, tc, A1, 6, CP[5], 5, ZF);
        for (int i = 0; i < tc; ++i) ops[oc++] = Op{0, t[i].a, t[i].b, 0};
        outs[1] = (unsigned char)ZF[5];
    }
    {
        int ZF[11] = {}; P8 t[160] = {}; int tc = 0;       // px2: WB + c2 copy
        oem2(WB, 6, CP[2], 5, ZF, t, tc);
        ok = ok && verify_merge144(t, 0, tc, WB, 6, CP[2], 5, ZF);
        for (int i = 0; i < tc; ++i) ops[oc++] = Op{0, t[i].a, t[i].b, 0};
        outs[2] = (unsigned char)ZF[5];
    }
    {
        int ZF[11] = {}; P8 t[160] = {}; int tc = 0;       // px3: QB win + c7 copy
        oem2(A3, 6, CP[7], 5, ZF, t, tc);
        ok = ok && verify_merge144(t, 0, tc, A3, 6, CP[7], 5, ZF);
        for (int i = 0; i < tc; ++i) ops[oc++] = Op{0, t[i].a, t[i].b, 0};
        outs[3] = (unsigned char)ZF[5];
    }
    {
        int ZF[11] = {}; P8 t[160] = {}; int tc = 0;       // px4: WC + c4 copy
        oem2(WC, 6, CP[4], 5, ZF, t, tc);
        ok = ok && verify_merge144(t, 0, tc, WC, 6, CP[4], 5, ZF);
        for (int i = 0; i < tc; ++i) ops[oc++] = Op{0, t[i].a, t[i].b, 0};
        outs[4] = (unsigned char)ZF[5];
    }
    {
        int ZF[11] = {}; P8 t[160] = {}; int tc = 0;       // px5: QC win + c9 copy
        oem2(A5, 6, CP[9], 5, ZF, t, tc);
        ok = ok && verify_merge144(t, 0, tc, A5, 6, CP[9], 5, ZF);
        for (int i = 0; i < tc; ++i) ops[oc++] = Op{0, t[i].a, t[i].b, 0};
        outs[5] = (unsigned char)ZF[5];
    }
    {
        int ZF[11] = {}; P8 t[160] = {}; int tc = 0;       // px6: WD + c6 copy
        oem2(WD, 6, CP[6], 5, ZF, t, tc);
        ok = ok && verify_merge144(t, 0, tc, WD, 6, CP[6], 5, ZF);
        for (int i = 0; i < tc; ++i) ops[oc++] = Op{0, t[i].a, t[i].b, 0};
        outs[6] = (unsigned char)ZF[5];
    }
    {
        int ZF[11] = {}; P8 t[160] = {}; int tc = 0;       // px7: QD win + c11
        oem2(A7, 6, C[11], 5, ZF, t, tc);
        ok = ok && verify_merge144(t, 0, tc, A7, 6, C[11], 5, ZF);
        for (int i = 0; i < tc; ++i) ops[oc++] = Op{0, t[i].a, t[i].b, 0};
        outs[7] = (unsigned char)ZF[5];
    }

    // Global backward slice with op-level pruning + copy liveness.
    bool need[144] = {};
    for (int i = 0; i < 8; ++i) need[outs[i]] = true;
    bool keep[640] = {};
    unsigned char opc[640] = {};
    for (int i = oc - 1; i >= 0; --i) {
        if (ops[i].t == 1) {                 // COPY a <- b
            if (need[ops[i].a]) {
                keep[i] = true;
                need[ops[i].b] = true;
                need[ops[i].a] = false;      // a redefined here
            }
        } else {                             // CE
            bool na = need[ops[i].a], nb = need[ops[i].b];
            if (na || nb) {
                keep[i] = true;
                opc[i] = (na && nb) ? 0 : (na ? 1 : 2);
                need[ops[i].a] = true;
                need[ops[i].b] = true;
            }
        }
    }

    Prog pr = {};
    pr.ok = ok;
    for (int i = 0; i < oc; ++i)
        if (keep[i]) {
            pr.p[pr.n] = ops[i];
            pr.p[pr.n].op = opc[i];
            ++pr.n;
        }
    for (int i = 0; i < 8; ++i) pr.outslot[i] = outs[i];
    return pr;
}

__device__ constexpr Prog PROG = build_prog();
static_assert(build_prog().ok, "interior merge verification failed");
static_assert(build_prog().n <= 600, "program overflow");

// ============================================================================
// Fused kernel
// ============================================================================

#define MF_C 3
#define MF_H 1024
#define MF_W 1024

// Boundary: 13272 px/channel (rows 0-1, rows 1021-1023, plus cols
// {0,1,1018..1023} of rows 2..1020) -> 39816 px -> 312 blocks of 128.
// Interior: 127 chunks (t in [0,127)) x 1019 rows x 3 channels, 1 block of
// 128 per (row, channel) -> 3057 blocks; thread t covers x = 8t+2 .. 8t+9.
#define NB_BOUND 312
#define NB_INNER 3057

__global__ __launch_bounds__(128)
void median_fused(const float* __restrict__ img, float* __restrict__ out) {
    constexpr int H = MF_H, W = MF_W;
    int blk = blockIdx.x;

    if (blk >= NB_BOUND) {
        // -------------------- Interior path --------------------
        int ib = blk - NB_BOUND;                 // 0 .. 3056
        int yrow = ib % 1019;
        int c = ib / 1019;
        int t = threadIdx.x;
        if (t >= 127) return;
        int y = yrow + 2;

        const float* base = img + ((size_t)c << 20) + (size_t)(y - 2) * W + 8 * t;

        float w[144];
#pragma unroll
        for (int k = 0; k < 5; ++k) {
            float4 a = *reinterpret_cast<const float4*>(base + (size_t)k * W);
            float4 b = *reinterpret_cast<const float4*>(base + (size_t)k * W + 4);
            float4 d = *reinterpret_cast<const float4*>(base + (size_t)k * W + 8);
            w[0 + k]  = a.x; w[5 + k]  = a.y; w[10 + k] = a.z; w[15 + k] = a.w;
            w[20 + k] = b.x; w[25 + k] = b.y; w[30 + k] = b.z; w[35 + k] = b.w;
            w[40 + k] = d.x; w[45 + k] = d.y; w[50 + k] = d.z; w[55 + k] = d.w;
        }

        // Unified sliced program: sorts, copies, shared merges, finals.
#pragma unroll
        for (int i = 0; i < PROG.n; ++i) {
            const int tt = PROG.p[i].t;
            const int a = PROG.p[i].a, b = PROG.p[i].b;
            const int op = PROG.p[i].op;
            if (tt == 1) {
                w[a] = w[b];
            } else if (op == 0) {
                float mn = fminf(w[a], w[b]);
                float mx = fmaxf(w[a], w[b]);
                w[a] = mn;
                w[b] = mx;
            } else if (op == 1) {
                w[a] = fminf(w[a], w[b]);
            } else {
                w[b] = fmaxf(w[a], w[b]);
            }
        }

        int x0 = 8 * t + 2;
        float* orow = out + ((size_t)c << 20) + (size_t)y * W;

        // x0 is even -> 8-byte aligned float2 stores.
#pragma unroll
        for (int p = 0; p < 4; ++p) {
            float2 s;
            s.x = w[PROG.outslot[2 * p]];
            s.y = w[PROG.outslot[2 * p + 1]];
            *reinterpret_cast<float2*>(orow + x0 + 2 * p) = s;
        }
        return;
    }

    // -------------------- Boundary path --------------------
    int idx = blk * 128 + threadIdx.x;           // 0 .. 39935
    if (idx >= 3 * 13272) return;
    int c = idx / 13272;
    int b = idx - c * 13272;

    int y, x;
    if (b < 2048) {                     // rows 0..1
        y = b >> 10; x = b & 1023;
    } else if (b < 5120) {              // rows 1021..1023
        int r = b - 2048; y = 1021 + (r >> 10); x = r & 1023;
    } else {                            // rows 2..1020, cols {0,1,1018..1023}
        int r = b - 5120;
        int q = r >> 3;
        int s = r & 7;
        y = 2 + q;
        x = (s < 2) ? s : 1016 + s;
    }

    const float* cimg = img + ((size_t)c << 20);

    float v[25];
    int inv = 0;

#pragma unroll
    for (int ky = 0; ky < 5; ++ky) {
        int yy = y + ky - 2;
        bool vy = (yy >= 0) && (yy <= H - 2);
        int  yc = min(max(yy, 0), H - 1);
        const float* row = cimg + (size_t)yc * W;
#pragma unroll
        for (int kx = 0; kx < 5; ++kx) {
            int xx = x + kx - 2;
            bool vx = (xx >= 0) && (xx <= W - 2);
            int  xc = min(max(xx, 0), W - 1);
            float val = __ldg(row + xc);
            if (!(vy && vx)) {
                val = __int_as_float((inv & 1) ? 0x7f800000u : 0xff800000u);
                ++inv;
            }
            v[ky * 5 + kx] = val;
        }
    }

#pragma unroll
    for (int i = 0; i < BNET.n; ++i) {
        const int a = BNET.p[i].a, b2 = BNET.p[i].b;
        const int op = BNET.p[i].op;
        if (op == 0) {
            float mn = fminf(v[a], v[b2]);
            float mx = fmaxf(v[a], v[b2]);
            v[a] = mn;
            v[b2] = mx;
        } else if (op == 1) {
            v[a] = fminf(v[a], v[b2]);
        } else {
            v[b2] = fmaxf(v[a], v[b2]);
        }
    }

    float s12 = v[12];
    float s13 = v[13];
    float hi  = (inv & 1) ? s13 : s12;
    out[((size_t)c << 20) + (size_t)y * W + x] = 0.5f * (s12 + hi);
}

extern "C" void kernel_launch(void* const* d_in, const int* in_sizes, int n_in,
                              void* d_out, int out_size) {
    const float* img = (const float*)d_in[0];
    float* out = (float*)d_out;
    median_fused<<<NB_BOUND + NB_INNER, 128>>>(img, out);
}

// round 12
// speedup vs baseline: 1.5051x; 1.5051x over previous
#include <cuda_runtime.h>

// ============================================================================
// Compile-time network machinery (all stages 0-1-verified at compile time).
//  - Batcher odd-even mergesort (power-of-2) + prefix restriction.
//  - Generalized odd-even merge on index lists (oem2).
//  - Global program over 144 slots, 8 pixels/thread, emitted in a PIPELINED
//    left-to-right order (sort cols -> quad -> finals -> next cols) to keep
//    peak register liveness low; one global backward slice with op-level
//    pruning (min-only / max-only / both) and copy liveness.
//  - Interval pruning theorem: for rank-12 of union(A sorted 20, B sorted 5),
//    A[i] has union position in [i, i+5]; A[0..6] always below rank 12,
//    A[13..19] always above; answer = index 5 of sorted(A[7..12] u B).
// ============================================================================

struct P8 { unsigned char a, b; };
struct Op { unsigned char t, a, b, op; };  // t: 0=CE, 1=COPY(a <- b)
struct CE3 { unsigned char a, b, op; };    // op: 0=both, 1=min-only, 2=max-only

constexpr void oem_merge(int lo, int n, int r, P8* out, int& cnt) {
    int m = r * 2;
    if (m < n) {
        oem_merge(lo,     n, m, out, cnt);
        oem_merge(lo + r, n, m, out, cnt);
        for (int i = lo + r; i + r < lo + n; i += m)
            out[cnt++] = P8{(unsigned char)i, (unsigned char)(i + r)};
    } else {
        out[cnt++] = P8{(unsigned char)lo, (unsigned char)(lo + r)};
    }
}

constexpr void oem_sort(int lo, int n, P8* out, int& cnt) {
    if (n > 1) {
        int m = n / 2;
        oem_sort(lo,     m, out, cnt);
        oem_sort(lo + m, m, out, cnt);
        oem_merge(lo, n, 1, out, cnt);
    }
}

// ---- sort-5 network: Batcher sort-8 restricted to slots < 5 (9 CEs).
struct Net5 { int n; P8 p[24]; };

constexpr Net5 build_sort5() {
    P8 all[64] = {};
    int cnt = 0;
    oem_sort(0, 8, all, cnt);
    Net5 s = {};
    for (int i = 0; i < cnt; ++i)
        if (all[i].a < 5 && all[i].b < 5)
            s.p[s.n++] = all[i];
    return s;
}

constexpr bool verify_sort5(const Net5& s) {
    for (int m = 0; m < 32; ++m) {
        int v[5] = {};
        for (int k = 0; k < 5; ++k) v[k] = (m >> k) & 1;
        for (int i = 0; i < s.n; ++i) {
            int a = s.p[i].a, b = s.p[i].b;
            if (v[a] > v[b]) { int t = v[a]; v[a] = v[b]; v[b] = t; }
        }
        for (int k = 0; k + 1 < 5; ++k)
            if (v[k] > v[k + 1]) return false;
    }
    return true;
}

static_assert(verify_sort5(build_sort5()), "sort5 network invalid");

// ---- Generalized odd-even merge on index lists (Knuth 5.2.2-style).
constexpr void oem2(const int* A, int m, const int* B, int n, int* Z,
                    P8* ce, int& cnt) {
    if (m == 0) { for (int i = 0; i < n; ++i) Z[i] = B[i]; return; }
    if (n == 0) { for (int i = 0; i < m; ++i) Z[i] = A[i]; return; }
    if (m == 1 && n == 1) {
        ce[cnt++] = P8{(unsigned char)A[0], (unsigned char)B[0]};
        Z[0] = A[0]; Z[1] = B[0];
        return;
    }
    int Ae[25] = {}, Ao[25] = {}, Be[25] = {}, Bo[25] = {};
    int nae = 0, nao = 0, nbe = 0, nbo = 0;
    for (int i = 0; i < m; ++i) { if (i & 1) Ao[nao++] = A[i]; else Ae[nae++] = A[i]; }
    for (int i = 0; i < n; ++i) { if (i & 1) Bo[nbo++] = B[i]; else Be[nbe++] = B[i]; }
    int E[25] = {}, O[25] = {};
    oem2(Ae, nae, Be, nbe, E, ce, cnt);
    oem2(Ao, nao, Bo, nbo, O, ce, cnt);
    int ne = nae + nbe, no = nao + nbo;
    Z[0] = E[0];
    int zi = 1;
    int i = 0;
    for (; i < no && i + 1 < ne; ++i) {
        ce[cnt++] = P8{(unsigned char)O[i], (unsigned char)E[i + 1]};
        Z[zi++] = O[i];
        Z[zi++] = E[i + 1];
    }
    for (; i < no; ++i) Z[zi++] = O[i];
    for (int j = i + 1; j < ne; ++j) Z[zi++] = E[j];
}

// Exhaustive 0-1 verification of one merge stage over a 144-slot space.
constexpr bool verify_merge144(const P8* ce, int ibeg, int iend,
                               const int* A, int m, const int* B, int n,
                               const int* Z) {
    for (int i = 0; i <= m; ++i) {
        for (int j = 0; j <= n; ++j) {
            int v[144] = {};
            for (int k = 0; k < m; ++k) v[A[k]] = (k >= m - i) ? 1 : 0;
            for (int k = 0; k < n; ++k) v[B[k]] = (k >= n - j) ? 1 : 0;
            for (int t = ibeg; t < iend; ++t) {
                int a = ce[t].a, b = ce[t].b;
                if (v[a] > v[b]) { int tmp = v[a]; v[a] = v[b]; v[b] = tmp; }
            }
            for (int k = 0; k + 1 < m + n; ++k)
                if (v[Z[k]] > v[Z[k + 1]]) return false;
        }
    }
    return true;
}

// ---- Boundary network: sort-25 sliced for {12,13} with op-level pruning.
struct Net { int n; CE3 p[256]; };

constexpr Net slice_net25(const P8* ce, int cnt, const bool* outputs_needed) {
    bool need[25] = {};
    for (int i = 0; i < 25; ++i) need[i] = outputs_needed[i];
    signed char op[256] = {};
    bool keep[256] = {};
    for (int i = cnt - 1; i >= 0; --i) {
        bool na = need[ce[i].a], nb = need[ce[i].b];
        if (!na && !nb) continue;
        keep[i] = true;
        op[i] = (na && nb) ? 0 : (na ? 1 : 2);
        need[ce[i].a] = true;
        need[ce[i].b] = true;
    }
    Net net = {};
    for (int i = 0; i < cnt; ++i)
        if (keep[i])
            net.p[net.n++] = CE3{ce[i].a, ce[i].b, (unsigned char)op[i]};
    return net;
}

constexpr Net build_boundary_net() {
    P8 all[256] = {};
    int cnt = 0;
    oem_sort(0, 32, all, cnt);
    P8 filt[256] = {};
    int fc = 0;
    for (int i = 0; i < cnt; ++i)
        if (all[i].a < 25 && all[i].b < 25)
            filt[fc++] = all[i];
    bool outs[25] = {};
    outs[12] = true;
    outs[13] = true;
    return slice_net25(filt, fc, outs);
}

__device__ constexpr Net BNET = build_boundary_net();

// ---- Emission helpers -------------------------------------------------------

constexpr void emit_sortcol(int j, Op* ops, int& oc) {
    Net5 s5 = build_sort5();
    for (int i = 0; i < s5.n; ++i)
        ops[oc++] = Op{0, (unsigned char)(5 * j + s5.p[i].a),
                          (unsigned char)(5 * j + s5.p[i].b), 0};
}

constexpr void emit_copy(const int* src, int cnt, int dstbase, int* dst,
                         Op* ops, int& oc) {
    for (int k = 0; k < cnt; ++k) {
        dst[k] = dstbase + k;
        ops[oc++] = Op{1, (unsigned char)(dstbase + k), (unsigned char)src[k], 0};
    }
}

constexpr void emit_mergev(const int* A, int m, const int* B, int n, int* Z,
                           Op* ops, int& oc, bool& ok) {
    P8 t[160] = {};
    int tc = 0;
    oem2(A, m, B, n, Z, t, tc);
    ok = ok && verify_merge144(t, 0, tc, A, m, B, n, Z);
    for (int i = 0; i < tc; ++i) ops[oc++] = Op{0, t[i].a, t[i].b, 0};
}

// ---- Global interior program over 144 slots, 8 pixels per thread.
// Slots 0..59: sorted local columns c0..c11 (col j at 5j..5j+4).
// 60..89: copies of cols {2,4,5,6,7,9}. 90..119: copies of m34,m56,m78.
// 120..143: quad windows WA,WB,WC,WD (6 each).
struct Prog { int n; Op p[600]; unsigned char outslot[8]; bool ok; };

constexpr Prog build_prog() {
    Op ops[640] = {};
    int oc = 0;
    bool ok = true;

    int C[12][5] = {};
    for (int j = 0; j < 12; ++j)
        for (int k = 0; k < 5; ++k) C[j][k] = 5 * j + k;

    int CP2[5] = {}, CP4[5] = {}, CP5[5] = {}, CP6[5] = {}, CP7[5] = {}, CP9[5] = {};
    int Z12[10] = {}, Z34[10] = {}, Z56[10] = {}, Z78[10] = {}, Z910[10] = {};
    int T34[10] = {}, T56[10] = {}, T78[10] = {};
    int QA[20] = {}, QB[20] = {}, QC[20] = {}, QD[20] = {};
    int WA[6] = {}, WB[6] = {}, WC[6] = {}, WD[6] = {};
    unsigned char outs[8] = {};

    // ---- Pipelined left-to-right emission ----
    // Stage A: cols 0..4, quad A, px0, px1.
    emit_sortcol(0, ops, oc);
    emit_sortcol(1, ops, oc);
    emit_sortcol(2, ops, oc);
    emit_copy(C[2], 5, 60, CP2, ops, oc);            // preserve sorted c2 (px2)
    emit_sortcol(3, ops, oc);
    emit_sortcol(4, ops, oc);
    emit_copy(C[4], 5, 65, CP4, ops, oc);            // preserve sorted c4 (px4)
    emit_mergev(C[1], 5, C[2], 5, Z12, ops, oc, ok); // destroys c1,c2 slots
    emit_mergev(C[3], 5, C[4], 5, Z34, ops, oc, ok); // destroys c3,c4 slots
    emit_copy(Z34, 10, 90, T34, ops, oc);            // preserve m34 (quad B)
    emit_mergev(Z12, 10, Z34, 10, QA, ops, oc, ok);  // quad A in place
    int A1[6] = {};
    for (int k = 0; k < 6; ++k) A1[k] = QA[7 + k];
    emit_copy(A1, 6, 120, WA, ops, oc);              // window copy for px0
    {
        int ZF[11] = {};                             // px0 = rank5(WA u c0)
        emit_mergev(WA, 6, C[0], 5, ZF, ops, oc, ok);
        outs[0] = (unsigned char)ZF[5];
    }
    emit_sortcol(5, ops, oc);
    emit_copy(C[5], 5, 70, CP5, ops, oc);            // preserve sorted c5 (px1)
    {
        int ZF[11] = {};                             // px1 = rank5(QAwin u c5')
        emit_mergev(A1, 6, CP5, 5, ZF, ops, oc, ok);
        outs[1] = (unsigned char)ZF[5];
    }

    // Stage B: cols 5..6 merged, quad B, px2, px3.
    emit_sortcol(6, ops, oc);
    emit_copy(C[6], 5, 75, CP6, ops, oc);            // preserve sorted c6 (px6)
    emit_mergev(C[5], 5, C[6], 5, Z56, ops, oc, ok);
    emit_copy(Z56, 10, 100, T56, ops, oc);           // preserve m56 (quad C)
    emit_mergev(T34, 10, Z56, 10, QB, ops, oc, ok);  // quad B
    int A3[6] = {};
    for (int k = 0; k < 6; ++k) A3[k] = QB[7 + k];
    emit_copy(A3, 6, 126, WB, ops, oc);
    {
        int ZF[11] = {};                             // px2 = rank5(WB u c2')
        emit_mergev(WB, 6, CP2, 5, ZF, ops, oc, ok);
        outs[2] = (unsigned char)ZF[5];
    }
    emit_sortcol(7, ops, oc);
    emit_copy(C[7], 5, 80, CP7, ops, oc);            // preserve sorted c7 (px3)
    {
        int ZF[11] = {};                             // px3 = rank5(QBwin u c7')
        emit_mergev(A3, 6, CP7, 5, ZF, ops, oc, ok);
        outs[3] = (unsigned char)ZF[5];
    }

    // Stage C: cols 7..8 merged, quad C, px4, px5.
    emit_sortcol(8, ops, oc);
    emit_mergev(C[7], 5, C[8], 5, Z78, ops, oc, ok);
    emit_copy(Z78, 10, 110, T78, ops, oc);           // preserve m78 (quad D)
    emit_mergev(T56, 10, Z78, 10, QC, ops, oc, ok);  // quad C
    int A5[6] = {};
    for (int k = 0; k < 6; ++k) A5[k] = QC[7 + k];
    emit_copy(A5, 6, 132, WC, ops, oc);
    {
        int ZF[11] = {};                             // px4 = rank5(WC u c4')
        emit_mergev(WC, 6, CP4, 5, ZF, ops, oc, ok);
        outs[4] = (unsigned char)ZF[5];
    }
    emit_sortcol(9, ops, oc);
    emit_copy(C[9], 5, 85, CP9, ops, oc);            // preserve sorted c9 (px5)
    {
        int ZF[11] = {};                             // px5 = rank5(QCwin u c9')
        emit_mergev(A5, 6, CP9, 5, ZF, ops, oc, ok);
        outs[5] = (unsigned char)ZF[5];
    }

    // Stage D: cols 9..10 merged, quad D, px6, px7.
    emit_sortcol(10, ops, oc);
    emit_mergev(C[9], 5, C[10], 5, Z910, ops, oc, ok);
    emit_mergev(T78, 10, Z910, 10, QD, ops, oc, ok); // quad D
    int A7[6] = {};
    for (int k = 0; k < 6; ++k) A7[k] = QD[7 + k];
    emit_copy(A7, 6, 138, WD, ops, oc);
    {
        int ZF[11] = {};                             // px6 = rank5(WD u c6')
        emit_mergev(WD, 6, CP6, 5, ZF, ops, oc, ok);
        outs[6] = (unsigned char)ZF[5];
    }
    emit_sortcol(11, ops, oc);
    {
        int ZF[11] = {};                             // px7 = rank5(QDwin u c11)
        emit_mergev(A7, 6, C[11], 5, ZF, ops, oc, ok);
        outs[7] = (unsigned char)ZF[5];
    }

    // Global backward slice with op-level pruning + copy liveness.
    bool need[144] = {};
    for (int i = 0; i < 8; ++i) need[outs[i]] = true;
    bool keep[640] = {};
    unsigned char opc[640] = {};
    for (int i = oc - 1; i >= 0; --i) {
        if (ops[i].t == 1) {                 // COPY a <- b
            if (need[ops[i].a]) {
                keep[i] = true;
                need[ops[i].b] = true;
                need[ops[i].a] = false;      // a redefined here
            }
        } else {                             // CE
            bool na = need[ops[i].a], nb = need[ops[i].b];
            if (na || nb) {
                keep[i] = true;
                opc[i] = (na && nb) ? 0 : (na ? 1 : 2);
                need[ops[i].a] = true;
                need[ops[i].b] = true;
            }
        }
    }

    Prog pr = {};
    pr.ok = ok;
    for (int i = 0; i < oc; ++i)
        if (keep[i]) {
            pr.p[pr.n] = ops[i];
            pr.p[pr.n].op = opc[i];
            ++pr.n;
        }
    for (int i = 0; i < 8; ++i) pr.outslot[i] = outs[i];
    return pr;
}

__device__ constexpr Prog PROG = build_prog();
static_assert(build_prog().ok, "interior merge verification failed");
static_assert(build_prog().n <= 600, "program overflow");

// ============================================================================
// Fused kernel
// ============================================================================

#define MF_C 3
#define MF_H 1024
#define MF_W 1024

// Boundary: 13272 px/channel (rows 0-1, rows 1021-1023, plus cols
// {0,1,1018..1023} of rows 2..1020) -> 39816 px -> 312 blocks of 128.
// Interior: 127 chunks (t in [0,127)) x 1019 rows x 3 channels, 1 block of
// 128 per (row, channel) -> 3057 blocks; thread t covers x = 8t+2 .. 8t+9.
#define NB_BOUND 312
#define NB_INNER 3057

__global__ __launch_bounds__(128)
void median_fused(const float* __restrict__ img, float* __restrict__ out) {
    constexpr int H = MF_H, W = MF_W;
    int blk = blockIdx.x;

    if (blk >= NB_BOUND) {
        // -------------------- Interior path --------------------
        int ib = blk - NB_BOUND;                 // 0 .. 3056
        int yrow = ib % 1019;
        int c = ib / 1019;
        int t = threadIdx.x;
        if (t >= 127) return;
        int y = yrow + 2;

        const float* base = img + ((size_t)c << 20) + (size_t)(y - 2) * W + 8 * t;

        float w[144];
#pragma unroll
        for (int k = 0; k < 5; ++k) {
            float4 a = *reinterpret_cast<const float4*>(base + (size_t)k * W);
            float4 b = *reinterpret_cast<const float4*>(base + (size_t)k * W + 4);
            float4 d = *reinterpret_cast<const float4*>(base + (size_t)k * W + 8);
            w[0 + k]  = a.x; w[5 + k]  = a.y; w[10 + k] = a.z; w[15 + k] = a.w;
            w[20 + k] = b.x; w[25 + k] = b.y; w[30 + k] = b.z; w[35 + k] = b.w;
            w[40 + k] = d.x; w[45 + k] = d.y; w[50 + k] = d.z; w[55 + k] = d.w;
        }

        // Unified sliced program in pipelined order.
#pragma unroll
        for (int i = 0; i < PROG.n; ++i) {
            const int tt = PROG.p[i].t;
            const int a = PROG.p[i].a, b = PROG.p[i].b;
            const int op = PROG.p[i].op;
            if (tt == 1) {
                w[a] = w[b];
            } else if (op == 0) {
                float mn = fminf(w[a], w[b]);
                float mx = fmaxf(w[a], w[b]);
                w[a] = mn;
                w[b] = mx;
            } else if (op == 1) {
                w[a] = fminf(w[a], w[b]);
            } else {
                w[b] = fmaxf(w[a], w[b]);
            }
        }

        int x0 = 8 * t + 2;
        float* orow = out + ((size_t)c << 20) + (size_t)y * W;

        // x0 is even -> 8-byte aligned float2 stores.
#pragma unroll
        for (int p = 0; p < 4; ++p) {
            float2 s;
            s.x = w[PROG.outslot[2 * p]];
            s.y = w[PROG.outslot[2 * p + 1]];
            *reinterpret_cast<float2*>(orow + x0 + 2 * p) = s;
        }
        return;
    }

    // -------------------- Boundary path --------------------
    int idx = blk * 128 + threadIdx.x;           // 0 .. 39935
    if (idx >= 3 * 13272) return;
    int c = idx / 13272;
    int b = idx - c * 13272;

    int y, x;
    if (b < 2048) {                     // rows 0..1
        y = b >> 10; x = b & 1023;
    } else if (b < 5120) {              // rows 1021..1023
        int r = b - 2048; y = 1021 + (r >> 10); x = r & 1023;
    } else {                            // rows 2..1020, cols {0,1,1018..1023}
        int r = b - 5120;
        int q = r >> 3;
        int s = r & 7;
        y = 2 + q;
        x = (s < 2) ? s : 1016 + s;
    }

    const float* cimg = img + ((size_t)c << 20);

    float v[25];
    int inv = 0;

#pragma unroll
    for (int ky = 0; ky < 5; ++ky) {
        int yy = y + ky - 2;
        bool vy = (yy >= 0) && (yy <= H - 2);
        int  yc = min(max(yy, 0), H - 1);
        const float* row = cimg + (size_t)yc * W;
#pragma unroll
        for (int kx = 0; kx < 5; ++kx) {
            int xx = x + kx - 2;
            bool vx = (xx >= 0) && (xx <= W - 2);
            int  xc = min(max(xx, 0), W - 1);
            float val = __ldg(row + xc);
            if (!(vy && vx)) {
                val = __int_as_float((inv & 1) ? 0x7f800000u : 0xff800000u);
                ++inv;
            }
            v[ky * 5 + kx] = val;
        }
    }

#pragma unroll
    for (int i = 0; i < BNET.n; ++i) {
        const int a = BNET.p[i].a, b2 = BNET.p[i].b;
        const int op = BNET.p[i].op;
        if (op == 0) {
            float mn = fminf(v[a], v[b2]);
            float mx = fmaxf(v[a], v[b2]);
            v[a] = mn;
            v[b2] = mx;
        } else if (op == 1) {
            v[a] = fminf(v[a], v[b2]);
        } else {
            v[b2] = fmaxf(v[a], v[b2]);
        }
    }

    float s12 = v[12];
    float s13 = v[13];
    float hi  = (inv & 1) ? s13 : s12;
    out[((size_t)c << 20) + (size_t)y * W + x] = 0.5f * (s12 + hi);
}

extern "C" void kernel_launch(void* const* d_in, const int* in_sizes, int n_in,
                              void* d_out, int out_size) {
    const float* img = (const float*)d_in[0];
    float* out = (float*)d_out;
    median_fused<<<NB_BOUND + NB_INNER, 128>>>(img, out);
}